// round 10
// baseline (speedup 1.0000x reference)
#include <cuda_runtime.h>
#include <cuda_bf16.h>

#define NB 32
#define HW 16384
#define NC 25

__device__ __forceinline__ float2 cmul(float2 a, float2 b) {
    return make_float2(fmaf(a.x, b.x, -a.y * b.y), fmaf(a.x, b.y, a.y * b.x));
}
__device__ __forceinline__ float2 cadd(float2 a, float2 b) {
    return make_float2(a.x + b.x, a.y + b.y);
}

// ---- f32x2 packed helpers ----
typedef unsigned long long u64;
__device__ __forceinline__ u64 pk2(float lo, float hi) {
    u64 r; asm("mov.b64 %0, {%1,%2};" : "=l"(r) : "f"(lo), "f"(hi)); return r;
}
__device__ __forceinline__ u64 fma2(u64 a, u64 b, u64 c) {
    u64 d; asm("fma.rn.f32x2 %0, %1, %2, %3;" : "=l"(d) : "l"(a), "l"(b), "l"(c)); return d;
}
__device__ __forceinline__ u64 mul2(u64 a, u64 b) {
    u64 d; asm("mul.rn.f32x2 %0, %1, %2;" : "=l"(d) : "l"(a), "l"(b)); return d;
}
__device__ __forceinline__ u64 add2(u64 a, u64 b) {
    u64 d; asm("add.rn.f32x2 %0, %1, %2;" : "=l"(d) : "l"(a), "l"(b)); return d;
}
__device__ __forceinline__ void upk2(u64 v, float& lo, float& hi) {
    asm("mov.b64 {%0,%1}, %2;" : "=f"(lo), "=f"(hi) : "l"(v));
}

// ---------------------------------------------------------------------------
// Fused kernel. grid = (32, NB), block = 256, 2 px/thread (one f32x2 stream).
// Each block: prefetch x -> redundant in-shared prep of the 56 per-b spectral
// constants -> evaluate. Constant table laid out so every coefficient PAIR is
// 16B-aligned -> LDS.128 loads (25 shared loads/thread instead of 49).
// ---------------------------------------------------------------------------
__global__ void __launch_bounds__(256)
qfused(const float* __restrict__ x, const float* __restrict__ qs,
       float* __restrict__ out) {
    __shared__ float2 sV[4];
    __shared__ float2 sU[3][4][4];
    __shared__ float2 sA[4][16];
    __shared__ float2 sP[4][NC];
    __shared__ float2 sCC[NC];
    __shared__ __align__(16) float2 sC2[56];   // u64 slots, duplicated lanes

    const int b = blockIdx.y;
    const int t = threadIdx.x;
    const float2 zero = make_float2(0.0f, 0.0f);

    // ---- prefetch x: one float4 = 2 pixels (DRAM latency hides under prep) ----
    const int base = b * (HW / 2) + blockIdx.x * 256 + t;
    float4 xx = reinterpret_cast<const float4*>(x)[base];

    // ---- Phase 1: ansatz-block unitaries, column-parallel (16 threads) ----
    if (t < 16) {
        const int s = t >> 2;
        const int c = t & 3;
        float2 col[4];
#pragma unroll
        for (int r = 0; r < 4; r++)
            col[r] = make_float2((r == c) ? 1.0f : 0.0f, 0.0f);

#pragma unroll
        for (int j = 0; j < 2; j++) {
#pragma unroll
            for (int k = 0; k < 2; k++) {
                const float* p = qs + ((((b * 4 + s) * 2 + j) * 2 + k) * 3);
                float th = p[0], ph = p[1], la = p[2];
                float ct = __cosf(th * 0.5f);
                float st = __sinf(th * 0.5f);
                float sl, cl, sp, cp;
                __sincosf(la, &sl, &cl);
                __sincosf(ph, &sp, &cp);
                float2 g00 = make_float2(ct, 0.0f);
                float2 g01 = make_float2(-cl * st, -sl * st);
                float2 g10 = make_float2(cp * st, sp * st);
                float2 epl = cmul(make_float2(cp, sp), make_float2(cl, sl));
                float2 g11 = make_float2(epl.x * ct, epl.y * ct);

                if (k == 0) {
                    float2 a0 = col[0], a1 = col[2];
                    col[0] = cadd(cmul(g00, a0), cmul(g01, a1));
                    col[2] = cadd(cmul(g10, a0), cmul(g11, a1));
                    float2 b0 = col[1], b1 = col[3];
                    col[1] = cadd(cmul(g00, b0), cmul(g01, b1));
                    col[3] = cadd(cmul(g10, b0), cmul(g11, b1));
                } else {
                    float2 a0 = col[0], a1 = col[1];
                    col[0] = cadd(cmul(g00, a0), cmul(g01, a1));
                    col[1] = cadd(cmul(g10, a0), cmul(g11, a1));
                    float2 b0 = col[2], b1 = col[3];
                    col[2] = cadd(cmul(g00, b0), cmul(g01, b1));
                    col[3] = cadd(cmul(g10, b0), cmul(g11, b1));
                }
            }
            float2 tmp = col[2]; col[2] = col[3]; col[3] = tmp;  // CNOT
        }

        if (s == 0) {
            if (c == 0) {
#pragma unroll
                for (int r = 0; r < 4; r++) sV[r] = col[r];
            }
        } else {
#pragma unroll
            for (int r = 0; r < 4; r++) sU[s - 1][r][c] = col[r];
        }
    }
    __syncthreads();

    // ---- Phase 2: polynomial evolution (16 threads) ----
    {
        const int slot = t;
        const int m = slot >> 2;
        const int n = slot & 3;

        if (t < 16) {
#pragma unroll
            for (int r = 0; r < 4; r++)
                sA[r][slot] = (slot == 0) ? sV[r] : zero;
        }
        __syncthreads();

        for (int i = 0; i < 3; i++) {
            float2 sh0 = zero, sh1 = zero, sh2 = zero, sh3 = zero;
            if (t < 16) {
                sh0 = sA[0][slot];
                if (n >= 1) sh1 = sA[1][slot - 1];
                if (m >= 1) sh2 = sA[2][slot - 4];
                if (m >= 1 && n >= 1) sh3 = sA[3][slot - 5];
            }
            __syncthreads();
            if (t < 16) {
                float2 nv[4];
#pragma unroll
                for (int r = 0; r < 4; r++) {
                    float2 acc = cmul(sU[i][r][0], sh0);
                    acc = cadd(acc, cmul(sU[i][r][1], sh1));
                    acc = cadd(acc, cmul(sU[i][r][2], sh2));
                    acc = cadd(acc, cmul(sU[i][r][3], sh3));
                    nv[r] = acc;
                }
#pragma unroll
                for (int r = 0; r < 4; r++) sA[r][slot] = nv[r];
            }
            __syncthreads();
        }
    }

    // ---- Phase 3: spectral coefficients, r-parallel (4 x 25 threads) ----
    {
        const int r  = t >> 5;
        const int kk = t & 31;
        if (t < 128 && kk < NC) {
            int mu, nu;
            if (kk == 0)      { mu = 0; nu = 0; }
            else if (kk < 4)  { mu = 0; nu = kk; }
            else              { mu = 1 + (kk - 4) / 7; nu = (kk - 4) % 7 - 3; }

            int mlo = (mu > 0) ? mu : 0;
            int nlo = (nu > 0) ? nu : 0;
            int nhi = (nu < 0) ? (3 + nu) : 3;

            float sgn = (r < 2) ? 1.0f : -1.0f;
            float2 acc = zero;
            for (int mm = mlo; mm <= 3; mm++) {
                for (int nn = nlo; nn <= nhi; nn++) {
                    float2 a  = sA[r][mm * 4 + nn];
                    float2 bb = sA[r][(mm - mu) * 4 + (nn - nu)];
                    acc.x += sgn * (a.x * bb.x + a.y * bb.y);
                    acc.y += sgn * (a.y * bb.x - a.x * bb.y);
                }
            }
            sP[r][kk] = acc;
        }
        __syncthreads();
        if (t < NC) {
            float2 s0 = sP[0][t], s1 = sP[1][t], s2 = sP[2][t], s3 = sP[3][t];
            sCC[t] = make_float2(s0.x + s1.x + s2.x + s3.x,
                                 s0.y + s1.y + s2.y + s3.y);
        }
        __syncthreads();
    }

    // ---- Phase 4: sign-folded duplicated table, pair-aligned layout ----
    // slots 0..7:  c00, 0, 2c01.x, -2c01.y, 2c02.x, -2c02.y, 2c03.x, -2c03.y
    // per mu (base = 8 + 16*mu): 2cm0.x, 2cm0.y, P1x, P1y, Q1x, Q1y,
    //                            P2x, P2y, Q2x, Q2y, P3x, P3y, Q3x, Q3y, 0, 0
    if (t < 56) {
        const int idx = t;
        float v;
        if (idx == 0) {
            v = sCC[0].x;
        } else if (idx == 1) {
            v = 0.0f;
        } else if (idx < 8) {
            int k = idx >> 1;                       // 1..3
            v = (idx & 1) ? (-2.0f * sCC[k].y) : (2.0f * sCC[k].x);
        } else {
            int j = idx - 8;
            int mu4 = j >> 4;
            int r = j & 15;
            int cbase = 4 + mu4 * 7 + 3;            // index of c_{mu,0}
            if (r == 0)      v = 2.0f * sCC[cbase].x;
            else if (r == 1) v = 2.0f * sCC[cbase].y;
            else if (r < 14) {
                int nu = (r - 2) / 4 + 1;
                int type = (r - 2) & 3;
                float2 cp = sCC[cbase + nu], cm = sCC[cbase - nu];
                if (type == 0)      v = 2.0f * (cp.x + cm.x);   // Px
                else if (type == 1) v = 2.0f * (cp.y + cm.y);   // Py
                else if (type == 2) v = -2.0f * (cp.y - cm.y);  // Qx
                else                v = 2.0f * (cp.x - cm.x);   // Qy
            } else {
                v = 0.0f;
            }
        }
        sC2[idx] = make_float2(v, v);
    }
    __syncthreads();

    // ---- Evaluation: one f32x2 stream (2 pixels), LDS.128 constant pairs ----
    const u64* C = (const u64*)sC2;
    const ulonglong2* C128 = (const ulonglong2*)sC2;

    float a0s, a0c, b0s, b0c, a1s, a1c, b1s, b1c;
    __sincosf(xx.x, &a0s, &a0c);
    __sincosf(xx.y, &b0s, &b0c);
    __sincosf(xx.z, &a1s, &a1c);
    __sincosf(xx.w, &b1s, &b1c);

    u64 A1x = pk2(a0c, a1c), A1y = pk2(a0s, a1s);
    u64 B1x = pk2(b0c, b1c), B1y = pk2(b0s, b1s);
    const u64 NEG1 = pk2(-1.0f, -1.0f);

    u64 nA1y = mul2(A1y, NEG1);
    u64 nB1y = mul2(B1y, NEG1);

    u64 A2x = fma2(A1x, A1x, mul2(A1y, nA1y));
    u64 tA  = mul2(A1x, A1y);
    u64 A2y = add2(tA, tA);
    u64 A3x = fma2(A2x, A1x, mul2(A2y, nA1y));
    u64 A3y = fma2(A2x, A1y, mul2(A2y, A1x));

    u64 B2x = fma2(B1x, B1x, mul2(B1y, nB1y));
    u64 tB  = mul2(B1x, B1y);
    u64 B2y = add2(tB, tB);
    u64 B3x = fma2(B2x, B1x, mul2(B2y, nB1y));
    u64 B3y = fma2(B2x, B1y, mul2(B2y, B1x));

    u64 nA2y = mul2(A2y, NEG1);
    u64 nA3y = mul2(A3y, NEG1);

    // mu = 0 row: ev = c00 + sum_k (ck_x * Bkx + ck_y * Bky), signs pre-folded
    u64 ev = C[0];
    {
        ulonglong2 p1 = C128[1];   // (2c01.x, -2c01.y)
        ev = fma2(p1.x, B1x, ev);
        ev = fma2(p1.y, B1y, ev);
        ulonglong2 p2 = C128[2];
        ev = fma2(p2.x, B2x, ev);
        ev = fma2(p2.y, B2y, ev);
        ulonglong2 p3 = C128[3];
        ev = fma2(p3.x, B3x, ev);
        ev = fma2(p3.y, B3y, ev);
    }

#pragma unroll
    for (int mu4 = 0; mu4 < 3; mu4++) {
        const ulonglong2* R = C128 + 4 + mu4 * 8;
        ulonglong2 c0 = R[0];
        u64 Tx = c0.x, Ty = c0.y;
        ulonglong2 P1 = R[1];
        Tx = fma2(P1.x, B1x, Tx); Ty = fma2(P1.y, B1x, Ty);
        ulonglong2 Q1 = R[2];
        Tx = fma2(Q1.x, B1y, Tx); Ty = fma2(Q1.y, B1y, Ty);
        ulonglong2 P2 = R[3];
        Tx = fma2(P2.x, B2x, Tx); Ty = fma2(P2.y, B2x, Ty);
        ulonglong2 Q2 = R[4];
        Tx = fma2(Q2.x, B2y, Tx); Ty = fma2(Q2.y, B2y, Ty);
        ulonglong2 P3 = R[5];
        Tx = fma2(P3.x, B3x, Tx); Ty = fma2(P3.y, B3x, Ty);
        ulonglong2 Q3 = R[6];
        Tx = fma2(Q3.x, B3y, Tx); Ty = fma2(Q3.y, B3y, Ty);

        u64 Ax  = (mu4 == 0) ? A1x  : (mu4 == 1) ? A2x  : A3x;
        u64 nAy = (mu4 == 0) ? nA1y : (mu4 == 1) ? nA2y : nA3y;
        ev = fma2(Ax, Tx, ev);
        ev = fma2(nAy, Ty, ev);
    }

    float lo, hi;
    upk2(ev, lo, hi);
    reinterpret_cast<float2*>(out)[base] = make_float2(lo, hi);
}

extern "C" void kernel_launch(void* const* d_in, const int* in_sizes, int n_in,
                              void* d_out, int out_size) {
    const float* x  = (const float*)d_in[0];   // (32, 16384, 2) float32
    const float* qs = (const float*)d_in[1];   // (32, 4, 2, 2, 3) float32
    float* out = (float*)d_out;                // (32, 16384) float32

    dim3 grid(32, NB);     // 1024 blocks, 256 threads, 2 px/thread
    qfused<<<grid, 256>>>(x, qs, out);
}